// round 16
// baseline (speedup 1.0000x reference)
#include <cuda_runtime.h>
#include <cuda_fp16.h>
#include <cstdint>
#include <cstddef>

#define NB   64
#define NIC  128
#define NOC  256
#define NHW  56
#define NDG  4
#define HW2  (NHW*NHW)

#define NTHREADS 256
#define BROWS 232                  // (2 out rows + 2 halo) x 58 w-positions

// ---------------- smem: B only (59.4 KB -> 2 CTAs/SM easily) ----------------
#define SM_BH   0
#define SMEM_TOTAL 59392

// A weights in DIRECT mma-fragment layout:
// per (d, oct, tap, mtile0..7, k0..7): 32 uint4; element [lane] = frag {a0,a1,a2,a3}
// (a0=[r][c],a1=[r+8][c],a2=[r][c+8],a3=[r+8][c+8]; r=lane>>2, c=(lane&3)*2)
__device__ __align__(16) uint4 g_wA4[NDG * 2 * 9 * 2048];

// ---------------- ptx helpers (baseline ISA only) ----------------
__device__ __forceinline__ uint32_t smem_u32(const void* p) {
    uint32_t a;
    asm("{ .reg .u64 t; cvta.to.shared.u64 t, %1; cvt.u32.u64 %0, t; }"
        : "=r"(a) : "l"(p));
    return a;
}
__device__ __forceinline__ void ldsm_x4(uint32_t* r, uint32_t addr) {
    asm volatile("ldmatrix.sync.aligned.m8n8.x4.shared.b16 {%0,%1,%2,%3}, [%4];"
                 : "=r"(r[0]), "=r"(r[1]), "=r"(r[2]), "=r"(r[3]) : "r"(addr));
}
__device__ __forceinline__ void ldsm_x2(uint32_t* r, uint32_t addr) {
    asm volatile("ldmatrix.sync.aligned.m8n8.x2.shared.b16 {%0,%1}, [%2];"
                 : "=r"(r[0]), "=r"(r[1]) : "r"(addr));
}
#define MMA_FP16(c, a, b)                                                     \
    asm volatile(                                                             \
        "mma.sync.aligned.m16n8k16.row.col.f32.f16.f16.f32 "                  \
        "{%0,%1,%2,%3},{%4,%5,%6,%7},{%8,%9},{%0,%1,%2,%3};"                  \
        : "+f"((c)[0]), "+f"((c)[1]), "+f"((c)[2]), "+f"((c)[3])              \
        : "r"((a)[0]), "r"((a)[1]), "r"((a)[2]), "r"((a)[3]),                 \
          "r"((b)[0]), "r"((b)[1]))

// ---------------------------------------------------------------------------
// Prep: masked weights -> fp16 in direct fragment layout.
// flat u32 index e = ((((d*2+oct)*9+tap)*8+mtile)*8+k)*128 + lane*4 + reg
// ---------------------------------------------------------------------------
__global__ void prep_weights_kernel(const float* __restrict__ base,
                                    const float* __restrict__ mask) {
    int e = blockIdx.x * blockDim.x + threadIdx.x;
    const int total = NDG * 2 * 9 * 8192;
    if (e >= total) return;
    int u    = e & 127;
    int lane = u >> 2, reg = u & 3;
    int t2   = e >> 7;
    int k    = t2 & 7;
    int t3   = t2 >> 3;
    int mtile = t3 & 7;
    int t4   = t3 >> 3;
    int tap  = t4 % 9;
    int t5   = t4 / 9;
    int oct  = t5 & 1;
    int d    = t5 >> 1;

    int oc  = mtile * 16 + (lane >> 2) + (reg & 1) * 8;
    int ic0 = k * 16 + (lane & 3) * 2 + ((reg >> 1) & 1) * 8;

    float w0 = base[((size_t)(oct * 128 + oc) * 128 + ic0) * 9 + tap] *
               mask[((size_t)d * 128 + ic0) * 9 + tap];
    float w1 = base[((size_t)(oct * 128 + oc) * 128 + ic0 + 1) * 9 + tap] *
               mask[((size_t)d * 128 + ic0 + 1) * 9 + tap];
    __half h0 = __float2half(w0);
    __half h1 = __float2half(w1);
    ((uint32_t*)g_wA4)[e] = (uint32_t)__half_as_ushort(h0) |
                            ((uint32_t)__half_as_ushort(h1) << 16);
}

// ---------------------------------------------------------------------------
// CTA = (row-pair hp, octile 128, b). 8 warps = 4 M-warps (32 oc) x 2 N-warps.
// A: LDG.128 directly to fragments (prefetched 1 round ahead). B: smem, built
// once. ZERO barriers in the main loop. 2 CTAs/SM.
// ---------------------------------------------------------------------------
__global__ __launch_bounds__(NTHREADS, 2)
void adaconv_mma_kernel(const float* __restrict__ x,
                        const int*   __restrict__ label,
                        float*       __restrict__ out) {
    extern __shared__ char smem[];
    const uint32_t sb = smem_u32(smem);

    const int tid  = threadIdx.x;
    const int wid  = tid >> 5;
    const int lane = tid & 31;
    const int warp_m = wid & 3;       // oc tile of 32 (mtiles 2*warp_m, +1)
    const int warp_n = wid >> 2;      // output row (0/1)

    const int hp  = blockIdx.x;       // 0..27
    const int oct = blockIdx.y;       // 0..1
    const int b   = blockIdx.z;       // 0..63
    const int h0  = hp * 2;

    int d = label[b];
    d = (d < 0) ? 0 : (d > NDG - 1 ? NDG - 1 : d);

    const float* __restrict__ xg = x + (size_t)b * NIC * HW2;
    // warp's A pointer: uint4 units; index = tap*2048 + mt*256 + k*32 + lane
    const uint4* __restrict__ wAw =
        g_wA4 + (size_t)((d * 2 + oct) * 9) * 2048 +
        (size_t)(warp_m * 2) * 256 + lane;

    // ---- build B once ----
    if (tid < BROWS) {
        const int np   = tid;
        const int rowl = np / 58;
        const int wq   = np - rowl * 58;
        const int h_in = h0 - 1 + rowl;
        const int w_in = wq - 1;
        const bool inb = (h_in >= 0 && h_in < NHW && w_in >= 0 && w_in < NHW);
        const float* __restrict__ xp = xg + (size_t)h_in * NHW + w_in;
        const uint32_t brow = (uint32_t)(np * 256);
        const uint32_t bx   = (uint32_t)((np & 7) << 4);
#pragma unroll 8
        for (int icp = 0; icp < 64; ++icp) {
            float v0 = 0.f, v1 = 0.f;
            if (inb) {
                v0 = xp[(size_t)(icp * 2) * HW2];
                v1 = xp[(size_t)(icp * 2 + 1) * HW2];
            }
            __half h0b = __float2half(v0);
            __half h1b = __float2half(v1);
            uint32_t hw = (uint32_t)__half_as_ushort(h0b) |
                          ((uint32_t)__half_as_ushort(h1b) << 16);
            uint32_t byte = brow + (((uint32_t)(icp * 4)) ^ bx);
            *(uint32_t*)(smem + SM_BH + byte) = hw;
        }
    }
    __syncthreads();   // the ONLY barrier

    float acc[2][7][4];
#pragma unroll
    for (int mt = 0; mt < 2; ++mt)
#pragma unroll
        for (int nt = 0; nt < 7; ++nt)
#pragma unroll
            for (int q = 0; q < 4; ++q) acc[mt][nt][q] = 0.f;

    // ---- hoisted B invariants ----
    const uint32_t akb  = (uint32_t)((lane >> 4) << 4);
    const uint32_t l15  = (uint32_t)(lane & 15);
    const uint32_t l7   = (uint32_t)(lane & 7);
    const uint32_t akb2 = (uint32_t)(((lane >> 3) & 1) << 4);

    uint4 ahv[2][2];          // [slot][mt] A fragments
    uint32_t bh[2][7][2];     // [slot][nt] B fragments

    // prologue: A(0, k=0)
    ahv[0][0] = wAw[0];
    ahv[0][1] = wAw[256];

    for (int tap = 0; tap < 9; ++tap) {
        const int dh = tap / 3, dw = tap % 3;
        const int nb = (warp_n + dh) * 58 + dw;

        const uint32_t bxx   = (uint32_t)(((nb + (lane & 7)) & 7) << 4);
        const uint32_t boff0 = sb + SM_BH + (uint32_t)((nb + l15) * 256);
        const uint32_t boff1 = boff0 + 16 * 256;
        const uint32_t boff2 = boff0 + 32 * 256;
        const uint32_t boff6 = sb + SM_BH + (uint32_t)((nb + 48 + l7) * 256);

        const uint4* __restrict__ wAt = wAw + tap * 2048;

        auto lb4 = [&](int p, int s, int k) {
            uint32_t kb = (uint32_t)(k * 32) + akb;
            uint32_t addr = (p == 0 ? boff0 : (p == 1 ? boff1 : boff2)) + (kb ^ bxx);
            uint32_t t[4];
            ldsm_x4(t, addr);
            bh[s][2 * p][0] = t[0]; bh[s][2 * p][1] = t[2];
            bh[s][2 * p + 1][0] = t[1]; bh[s][2 * p + 1][1] = t[3];
        };
        auto lb2 = [&](int s, int k) {
            uint32_t kb2 = (uint32_t)(k * 32) + akb2;
            uint32_t t[2];
            ldsm_x2(t, boff6 + (kb2 ^ bxx));
            bh[s][6][0] = t[0]; bh[s][6][1] = t[1];
        };

        // B frags for (tap, k=0) into slot 0 (slot 0 free at tap start)
        lb4(0, 0, 0); lb4(1, 0, 0); lb4(2, 0, 0); lb2(0, 0);

#pragma unroll
        for (int k = 0; k < 8; ++k) {
            const int s = k & 1, ns = s ^ 1;

            // prefetch A for next round (next tap's k0 at k==7)
            if (k < 7) {
                ahv[ns][0] = wAt[(k + 1) * 32];
                ahv[ns][1] = wAt[256 + (k + 1) * 32];
            } else if (tap < 8) {
                ahv[0][0] = wAt[2048];
                ahv[0][1] = wAt[2048 + 256];
            }

            const uint32_t* a0 = (const uint32_t*)&ahv[s][0];
            const uint32_t* a1 = (const uint32_t*)&ahv[s][1];

            MMA_FP16(acc[0][0], a0, bh[s][0]);
            MMA_FP16(acc[0][1], a0, bh[s][1]);
            if (k < 7) lb4(0, ns, k + 1);
            MMA_FP16(acc[0][2], a0, bh[s][2]);
            MMA_FP16(acc[0][3], a0, bh[s][3]);
            if (k < 7) lb4(1, ns, k + 1);
            MMA_FP16(acc[0][4], a0, bh[s][4]);
            MMA_FP16(acc[0][5], a0, bh[s][5]);
            if (k < 7) lb4(2, ns, k + 1);
            MMA_FP16(acc[0][6], a0, bh[s][6]);
            MMA_FP16(acc[1][0], a1, bh[s][0]);
            if (k < 7) lb2(ns, k + 1);
            MMA_FP16(acc[1][1], a1, bh[s][1]);
            MMA_FP16(acc[1][2], a1, bh[s][2]);
            MMA_FP16(acc[1][3], a1, bh[s][3]);
            MMA_FP16(acc[1][4], a1, bh[s][4]);
            MMA_FP16(acc[1][5], a1, bh[s][5]);
            MMA_FP16(acc[1][6], a1, bh[s][6]);
        }
    }

    // ---- epilogue ----
    const int h = h0 + warp_n;
    const int col0 = (lane & 3) * 2;
    const int r0 = lane >> 2;
#pragma unroll
    for (int mt = 0; mt < 2; ++mt) {
        int ocb = oct * 128 + warp_m * 32 + mt * 16;
        float* __restrict__ o0 = out + ((size_t)b * NOC + ocb + r0) * HW2 + (size_t)h * NHW;
        float* __restrict__ o1 = o0 + (size_t)8 * HW2;
#pragma unroll
        for (int nt = 0; nt < 7; ++nt) {
            int w = nt * 8 + col0;
            *(float2*)(o0 + w) = make_float2(acc[mt][nt][0], acc[mt][nt][1]);
            *(float2*)(o1 + w) = make_float2(acc[mt][nt][2], acc[mt][nt][3]);
        }
    }
}

// ---------------------------------------------------------------------------
extern "C" void kernel_launch(void* const* d_in, const int* in_sizes, int n_in,
                              void* d_out, int out_size) {
    const float* x     = nullptr;
    const int*   label = nullptr;
    const float* base  = nullptr;
    const float* mask  = nullptr;
    for (int i = 0; i < n_in; ++i) {
        switch (in_sizes[i]) {
            case 25690112: x     = (const float*)d_in[i]; break;
            case 64:       label = (const int*)  d_in[i]; break;
            case 294912:   base  = (const float*)d_in[i]; break;
            case 4608:     mask  = (const float*)d_in[i]; break;
            default: break;
        }
    }
    if (!x     && n_in > 0) x     = (const float*)d_in[0];
    if (!label && n_in > 1) label = (const int*)  d_in[1];
    if (!base  && n_in > 2) base  = (const float*)d_in[2];
    if (!mask  && n_in > 3) mask  = (const float*)d_in[3];

    float* out = (float*)d_out;

    {
        const int total = NDG * 2 * 9 * 8192;
        prep_weights_kernel<<<(total + 255) / 256, 256>>>(base, mask);
    }
    cudaFuncSetAttribute(adaconv_mma_kernel,
                         cudaFuncAttributeMaxDynamicSharedMemorySize, SMEM_TOTAL);
    {
        dim3 grid(28, 2, NB);
        adaconv_mma_kernel<<<grid, NTHREADS, SMEM_TOTAL>>>(x, label, out);
    }
}

// round 17
// speedup vs baseline: 1.2217x; 1.2217x over previous
#include <cuda_runtime.h>
#include <cuda_fp16.h>
#include <cstdint>
#include <cstddef>

#define NB   64
#define NIC  128
#define NOC  256
#define NHW  56
#define NDG  4
#define HW2  (NHW*NHW)

#define NTHREADS 256
#define BROWS 232                  // (2 out rows + 2 halo) x 58 w-positions

// ---------------- smem layout (106 KB + mbars -> 2 CTAs/SM) ----------------
#define SM_BH   0                  // 232 * 256 B = 59392
#define SM_A    59392              // 3 slots x 16 KB (A k-half slabs)
#define SM_MB   108544             // 6 mbarriers (3 full + 3 empty)
#define SMEM_TOTAL 108608

// Pre-swizzled fp16 weights, HALF-SLAB layout:
// per (d, octile, tap): [half(2)][oc(128)][128B swizzled] = 32 KB
__device__ __align__(16) __half g_w2[NDG * 2 * 9 * 16384];

// ---------------- ptx helpers (baseline ISA only) ----------------
__device__ __forceinline__ uint32_t smem_u32(const void* p) {
    uint32_t a;
    asm("{ .reg .u64 t; cvta.to.shared.u64 t, %1; cvt.u32.u64 %0, t; }"
        : "=r"(a) : "l"(p));
    return a;
}
__device__ __forceinline__ void ldsm_x4(uint32_t* r, uint32_t addr) {
    asm volatile("ldmatrix.sync.aligned.m8n8.x4.shared.b16 {%0,%1,%2,%3}, [%4];"
                 : "=r"(r[0]), "=r"(r[1]), "=r"(r[2]), "=r"(r[3]) : "r"(addr));
}
__device__ __forceinline__ void ldsm_x2(uint32_t* r, uint32_t addr) {
    asm volatile("ldmatrix.sync.aligned.m8n8.x2.shared.b16 {%0,%1}, [%2];"
                 : "=r"(r[0]), "=r"(r[1]) : "r"(addr));
}
__device__ __forceinline__ void cp_async16(uint32_t saddr, const void* gptr) {
    asm volatile("cp.async.cg.shared.global [%0], [%1], 16;"
                 :: "r"(saddr), "l"(gptr) : "memory");
}
#define CP_COMMIT() asm volatile("cp.async.commit_group;" ::: "memory")
#define CP_WAIT0()  asm volatile("cp.async.wait_group 0;" ::: "memory")
#define CP_WAIT1()  asm volatile("cp.async.wait_group 1;" ::: "memory")

#define MBAR_INIT(mb, c)  asm volatile("mbarrier.init.shared.b64 [%0], %1;" :: "r"(mb), "r"(c) : "memory")
#define MBAR_ARRIVE(mb)   asm volatile("mbarrier.arrive.shared.b64 _, [%0];" :: "r"(mb) : "memory")

__device__ __forceinline__ void mbar_wait(uint32_t mbar, uint32_t parity) {
    uint32_t done;
    asm volatile(
        "{\n\t.reg .pred p;\n\t"
        "mbarrier.try_wait.parity.shared.b64 p, [%1], %2;\n\t"
        "selp.b32 %0, 1, 0, p;\n\t}" : "=r"(done) : "r"(mbar), "r"(parity) : "memory");
    if (!done) {
        asm volatile(
            "{\n\t.reg .pred P1;\n\tW_%=:\n\t"
            "mbarrier.try_wait.parity.shared.b64 P1, [%0], %1;\n\t"
            "@P1 bra.uni D_%=;\n\tbra.uni W_%=;\n\tD_%=:\n\t}"
            :: "r"(mbar), "r"(parity) : "memory");
    }
}

#define MMA_FP16(c, a, b)                                                     \
    asm volatile(                                                             \
        "mma.sync.aligned.m16n8k16.row.col.f32.f16.f16.f32 "                  \
        "{%0,%1,%2,%3},{%4,%5,%6,%7},{%8,%9},{%0,%1,%2,%3};"                  \
        : "+f"((c)[0]), "+f"((c)[1]), "+f"((c)[2]), "+f"((c)[3])              \
        : "r"((a)[0]), "r"((a)[1]), "r"((a)[2]), "r"((a)[3]),                 \
          "r"((b)[0]), "r"((b)[1]))

// ---------------------------------------------------------------------------
// Prep: masked weights -> fp16, half-slab swizzled image.
// byte = half*16384 + oc*128 + (((ic&63)*2) ^ ((oc&7)<<4)), half = ic>>6
// ---------------------------------------------------------------------------
__global__ void prep_weights_kernel(const float* __restrict__ base,
                                    const float* __restrict__ mask) {
    int e = blockIdx.x * blockDim.x + threadIdx.x;
    const int total = NDG * 2 * 9 * 128 * 128;
    if (e >= total) return;
    int ic  = e % 128;
    int t2  = e / 128;
    int oc  = t2 % 128;
    int t3  = t2 / 128;
    int tap = t3 % 9;
    int t4  = t3 / 9;
    int oct = t4 % 2;
    int d   = t4 / 2;

    float w = base[((size_t)(oct * 128 + oc) * 128 + ic) * 9 + tap] *
              mask[((size_t)d * 128 + ic) * 9 + tap];

    uint32_t byte = (uint32_t)((ic >> 6) * 16384 + oc * 128 +
                               (((ic & 63) * 2) ^ ((oc & 7) << 4)));
    size_t slab = (size_t)((d * 2 + oct) * 9 + tap) * 16384;
    g_w2[slab + (byte >> 1)] = __float2half(w);
}

// ---------------------------------------------------------------------------
// CTA = (row-pair hp, octile 128, b). 8 warps = 4 M-warps (32 oc) x 2 N-warps.
// A: 3-slot 16KB ring driven by mbarrier produce/consume (NO __syncthreads in
// the main loop). B: built once, static. 2 CTAs/SM.
// ---------------------------------------------------------------------------
__global__ __launch_bounds__(NTHREADS, 2)
void adaconv_mma_kernel(const float* __restrict__ x,
                        const int*   __restrict__ label,
                        float*       __restrict__ out) {
    extern __shared__ char smem[];
    const uint32_t sb = smem_u32(smem);

    const int tid  = threadIdx.x;
    const int wid  = tid >> 5;
    const int lane = tid & 31;
    const int warp_m = wid & 3;       // oc tile of 32
    const int warp_n = wid >> 2;      // output row (0/1)

    const int hp  = blockIdx.x;       // 0..27
    const int oct = blockIdx.y;       // 0..1
    const int b   = blockIdx.z;       // 0..63
    const int h0  = hp * 2;

    int d = label[b];
    d = (d < 0) ? 0 : (d > NDG - 1 ? NDG - 1 : d);

    const float* __restrict__ xg = x + (size_t)b * NIC * HW2;
    const char* __restrict__ wbase =
        (const char*)(g_w2 + (size_t)((d * 2 + oct) * 9) * 16384);

    const uint32_t mb_full  = sb + SM_MB;        // 3 x 8B
    const uint32_t mb_empty = sb + SM_MB + 24;   // 3 x 8B

    if (tid == 0) {
#pragma unroll
        for (int s = 0; s < 3; ++s) {
            MBAR_INIT(mb_full  + s * 8, 8);   // 8 warp-arrives per fill
            MBAR_INIT(mb_empty + s * 8, 8);   // 8 warp-arrives per consume
        }
    }

    // ---- prologue: fill slots 0,1 with half-slabs 0,1 (tap0 h0,h1) ----
    {
#pragma unroll
        for (int j = 0; j < 4; ++j) {
            cp_async16(sb + SM_A + tid * 16 + j * 4096, wbase + tid * 16 + j * 4096);
            cp_async16(sb + SM_A + 16384 + tid * 16 + j * 4096,
                       wbase + 16384 + tid * 16 + j * 4096);
        }
        CP_COMMIT();
    }

    // ---- build B once (overlaps prologue cp) ----
    if (tid < BROWS) {
        const int np   = tid;
        const int rowl = np / 58;
        const int wq   = np - rowl * 58;
        const int h_in = h0 - 1 + rowl;
        const int w_in = wq - 1;
        const bool inb = (h_in >= 0 && h_in < NHW && w_in >= 0 && w_in < NHW);
        const float* __restrict__ xp = xg + (size_t)h_in * NHW + w_in;
        const uint32_t brow = (uint32_t)(np * 256);
        const uint32_t bx   = (uint32_t)((np & 7) << 4);
#pragma unroll 8
        for (int icp = 0; icp < 64; ++icp) {
            float v0 = 0.f, v1 = 0.f;
            if (inb) {
                v0 = xp[(size_t)(icp * 2) * HW2];
                v1 = xp[(size_t)(icp * 2 + 1) * HW2];
            }
            __half h0b = __float2half(v0);
            __half h1b = __float2half(v1);
            uint32_t hw = (uint32_t)__half_as_ushort(h0b) |
                          ((uint32_t)__half_as_ushort(h1b) << 16);
            uint32_t byte = brow + (((uint32_t)(icp * 4)) ^ bx);
            *(uint32_t*)(smem + SM_BH + byte) = hw;
        }
    }
    __syncthreads();   // B + mbar init visible; the ONLY CTA-wide barrier

    // prologue full signals
    CP_WAIT0();
    __syncwarp();
    if (lane == 0) { MBAR_ARRIVE(mb_full); MBAR_ARRIVE(mb_full + 8); }

    float acc[2][7][4];
#pragma unroll
    for (int mt = 0; mt < 2; ++mt)
#pragma unroll
        for (int nt = 0; nt < 7; ++nt)
#pragma unroll
            for (int q = 0; q < 4; ++q) acc[mt][nt][q] = 0.f;

    // ---- hoisted invariants ----
    const int arow     = warp_m * 32 + (lane & 15);
    const uint32_t akb = (uint32_t)((lane >> 4) << 4);
    uint32_t aoff[2], ax[2];
#pragma unroll
    for (int mt = 0; mt < 2; ++mt) {
        int r = arow + mt * 16;
        aoff[mt] = (uint32_t)(r * 128);
        ax[mt]   = (uint32_t)((r & 7) << 4);
    }
    const uint32_t l15  = (uint32_t)(lane & 15);
    const uint32_t l7   = (uint32_t)(lane & 7);
    const uint32_t akb2 = (uint32_t)(((lane >> 3) & 1) << 4);

    uint32_t ah[2][2][4], bh[2][7][2];
    int fp[3] = {0, 0, 0}, ep[3] = {0, 0, 0};

#pragma unroll 1
    for (int i = 0; i < 18; ++i) {
        const int s     = i % 3;
        const int tap   = i >> 1;
        const int hhalf = i & 1;
        const int dh = tap / 3, dw = tap % 3;
        const int nb = (warp_n + dh) * 58 + dw;

        const uint32_t bxx   = (uint32_t)(((nb + (lane & 7)) & 7) << 4);
        const uint32_t boff0 = sb + SM_BH + (uint32_t)((nb + l15) * 256);
        const uint32_t boff1 = boff0 + 16 * 256;
        const uint32_t boff2 = boff0 + 32 * 256;
        const uint32_t boff6 = sb + SM_BH + (uint32_t)((nb + 48 + l7) * 256);
        const uint32_t ab    = sb + SM_A + (uint32_t)s * 16384;

        auto lb4 = [&](int p, int sl, int kg) {
            uint32_t kb = (uint32_t)(kg * 32) + akb;
            uint32_t addr = (p == 0 ? boff0 : (p == 1 ? boff1 : boff2)) + (kb ^ bxx);
            uint32_t t[4];
            ldsm_x4(t, addr);
            bh[sl][2 * p][0] = t[0]; bh[sl][2 * p][1] = t[2];
            bh[sl][2 * p + 1][0] = t[1]; bh[sl][2 * p + 1][1] = t[3];
        };
        auto lb2 = [&](int sl, int kg) {
            uint32_t kb2 = (uint32_t)(kg * 32) + akb2;
            uint32_t t[2];
            ldsm_x2(t, boff6 + (kb2 ^ bxx));
            bh[sl][6][0] = t[0]; bh[sl][6][1] = t[1];
        };
        auto la = [&](int mt, int sl, int kl) {
            uint32_t kbl = (uint32_t)(kl * 32) + akb;
            ldsm_x4(ah[sl][mt], ab + aoff[mt] + (kbl ^ ax[mt]));
        };

        // ---- preload B(k0 of this half-slab) BEFORE the full-wait (B static)
        const int kg0 = hhalf * 4;
        lb4(0, 0, kg0); lb4(1, 0, kg0); lb4(2, 0, kg0); lb2(0, kg0);

        // ---- signal fill of half-slab i (issued at iter i-2) ----
        if (i >= 2) {
            if (i <= 16) { CP_WAIT1(); } else { CP_WAIT0(); }
            __syncwarp();
            if (lane == 0) MBAR_ARRIVE(mb_full + s * 8);
        }

        // ---- consume: wait A(half-slab i) ----
        mbar_wait(mb_full + s * 8, (uint32_t)fp[s]); fp[s] ^= 1;

        la(0, 0, 0); la(1, 0, 0);

        // 4 rounds; loads for r+1 interleaved
#pragma unroll
        for (int r = 0; r < 4; ++r) {
            const int sl = r & 1, ns = sl ^ 1;
            const bool ld = (r < 3);
            const int kl = r + 1;          // A k-local
            const int kg = kg0 + r + 1;    // B k-global

            const uint32_t* a0 = ah[sl][0];
            const uint32_t* a1 = ah[sl][1];

            if (ld) { la(0, ns, kl); la(1, ns, kl); }
            MMA_FP16(acc[0][0], a0, bh[sl][0]);
            MMA_FP16(acc[0][1], a0, bh[sl][1]);
            if (ld) lb4(0, ns, kg);
            MMA_FP16(acc[0][2], a0, bh[sl][2]);
            MMA_FP16(acc[0][3], a0, bh[sl][3]);
            if (ld) lb4(1, ns, kg);
            MMA_FP16(acc[0][4], a0, bh[sl][4]);
            MMA_FP16(acc[0][5], a0, bh[sl][5]);
            if (ld) lb4(2, ns, kg);
            MMA_FP16(acc[0][6], a0, bh[sl][6]);
            MMA_FP16(acc[1][0], a1, bh[sl][0]);
            if (ld) lb2(ns, kg);
            MMA_FP16(acc[1][1], a1, bh[sl][1]);
            MMA_FP16(acc[1][2], a1, bh[sl][2]);
            MMA_FP16(acc[1][3], a1, bh[sl][3]);
            MMA_FP16(acc[1][4], a1, bh[sl][4]);
            MMA_FP16(acc[1][5], a1, bh[sl][5]);
            MMA_FP16(acc[1][6], a1, bh[sl][6]);
        }

        __syncwarp();
        if (lane == 0) MBAR_ARRIVE(mb_empty + s * 8);

        // ---- produce half-slab i+2 into slot (i+2)%3 ----
        if (i <= 15) {
            const int s2 = (i + 2) % 3;
            if (i > 0) { mbar_wait(mb_empty + s2 * 8, (uint32_t)ep[s2]); ep[s2] ^= 1; }
            const int hs = i + 2;
            const char* gsrc = wbase + (size_t)(hs >> 1) * 32768 + (size_t)(hs & 1) * 16384;
            uint32_t dst = sb + SM_A + (uint32_t)s2 * 16384;
#pragma unroll
            for (int j = 0; j < 4; ++j)
                cp_async16(dst + tid * 16 + j * 4096, gsrc + tid * 16 + j * 4096);
            CP_COMMIT();
        }
    }

    // ---- epilogue ----
    const int h = h0 + warp_n;
    const int col0 = (lane & 3) * 2;
    const int r0 = lane >> 2;
#pragma unroll
    for (int mt = 0; mt < 2; ++mt) {
        int ocb = oct * 128 + warp_m * 32 + mt * 16;
        float* __restrict__ o0 = out + ((size_t)b * NOC + ocb + r0) * HW2 + (size_t)h * NHW;
        float* __restrict__ o1 = o0 + (size_t)8 * HW2;
#pragma unroll
        for (int nt = 0; nt < 7; ++nt) {
            int w = nt * 8 + col0;
            *(float2*)(o0 + w) = make_float2(acc[mt][nt][0], acc[mt][nt][1]);
            *(float2*)(o1 + w) = make_float2(acc[mt][nt][2], acc[mt][nt][3]);
        }
    }
}

// ---------------------------------------------------------------------------
extern "C" void kernel_launch(void* const* d_in, const int* in_sizes, int n_in,
                              void* d_out, int out_size) {
    const float* x     = nullptr;
    const int*   label = nullptr;
    const float* base  = nullptr;
    const float* mask  = nullptr;
    for (int i = 0; i < n_in; ++i) {
        switch (in_sizes[i]) {
            case 25690112: x     = (const float*)d_in[i]; break;
            case 64:       label = (const int*)  d_in[i]; break;
            case 294912:   base  = (const float*)d_in[i]; break;
            case 4608:     mask  = (const float*)d_in[i]; break;
            default: break;
        }
    }
    if (!x     && n_in > 0) x     = (const float*)d_in[0];
    if (!label && n_in > 1) label = (const int*)  d_in[1];
    if (!base  && n_in > 2) base  = (const float*)d_in[2];
    if (!mask  && n_in > 3) mask  = (const float*)d_in[3];

    float* out = (float*)d_out;

    {
        const int total = NDG * 2 * 9 * 128 * 128;
        prep_weights_kernel<<<(total + 255) / 256, 256>>>(base, mask);
    }
    cudaFuncSetAttribute(adaconv_mma_kernel,
                         cudaFuncAttributeMaxDynamicSharedMemorySize, SMEM_TOTAL);
    {
        dim3 grid(28, 2, NB);
        adaconv_mma_kernel<<<grid, NTHREADS, SMEM_TOTAL>>>(x, label, out);
    }
}